// round 6
// baseline (speedup 1.0000x reference)
#include <cuda_runtime.h>
#include <cstdint>

// ============================================================================
// relu(x @ W^T + b):  B=131072, D_IN=D_OUT=256, fp32 in/out.
//
// mma.sync m16n8k8 tf32 (sm_80+ PTX -> compiles under compute_103 family
// target; tcgen05.ld/st/wait are sm_103a-only and rejected by this toolchain).
// RN-converted tf32 operands (cvt.rna) for unbiased rounding: rel_err ~4e-4.
//
// CTA tile M=128 x N=256 (full N -> x read once), 512 threads / 16 warps,
// warp tile 64x32, 64 fp32 accum regs/thread. K streamed in 8 chunks of 32
// through a 2-stage pitch-36-padded SMEM buffer (conflict-free fragment LDS,
// aligned float4 STS). Register-prefetch of next chunk overlaps compute.
// ============================================================================

#define DEVINL static __device__ __forceinline__

static constexpr int DIM     = 256;
static constexpr int TILE_M  = 128;
static constexpr int KC      = 32;                 // K per chunk
static constexpr int NCH     = DIM / KC;           // 8 chunks
static constexpr int PITCH   = 36;                 // padded floats per row-chunk
static constexpr int THREADS = 512;

static constexpr int A_WORDS     = TILE_M * PITCH;        // 4608
static constexpr int B_WORDS     = DIM * PITCH;           // 9216
static constexpr int STAGE_WORDS = A_WORDS + B_WORDS;     // 13824
static constexpr int BIAS_WORDS  = 256;
static constexpr int SMEM_BYTES  = (BIAS_WORDS + 2 * STAGE_WORDS) * 4; // 111616

DEVINL uint32_t f2tf(float f) {
    uint32_t r;
    asm("cvt.rna.tf32.f32 %0, %1;" : "=r"(r) : "f"(f));
    return r;
}

DEVINL void mma_tf32(float* d, const uint32_t* a, const uint32_t* b) {
    asm volatile(
        "mma.sync.aligned.m16n8k8.row.col.f32.tf32.tf32.f32 "
        "{%0,%1,%2,%3}, {%4,%5,%6,%7}, {%8,%9}, {%0,%1,%2,%3};"
        : "+f"(d[0]), "+f"(d[1]), "+f"(d[2]), "+f"(d[3])
        : "r"(a[0]), "r"(a[1]), "r"(a[2]), "r"(a[3]),
          "r"(b[0]), "r"(b[1]));
}

__global__ void __launch_bounds__(THREADS, 1)
gemm_bias_relu_mma(const float4* __restrict__ x4,
                   const float4* __restrict__ w4,
                   const float*  __restrict__ bias,
                   float2*       __restrict__ out2) {
    extern __shared__ uint32_t sm[];
    float*    bsm  = (float*)sm;
    uint32_t* stg0 = sm + BIAS_WORDS;
    uint32_t* stg1 = sm + BIAS_WORDS + STAGE_WORDS;

    const int  tid    = threadIdx.x;
    const long m_base = (long)blockIdx.x * TILE_M;

    if (tid < 256) bsm[tid] = bias[tid];

    // ---------------- loader mapping (all 512 threads) ----------------
    // Each thread owns: A rows {lr, lr+64}, B rows {lr + 64j, j=0..3},
    // float4 group kg within the 32-wide K chunk.
    const int lr = tid >> 3;   // 0..63
    const int kg = tid & 7;    // 0..7

    const long ga0 = (m_base + lr)      * 64 + kg;   // x row pitch = 64 float4
    const long ga1 = (m_base + lr + 64) * 64 + kg;
    const long gb0 = (long)lr * 64 + kg;             // W row pitch = 64 float4

    const int sa0 = lr        * PITCH + kg * 4;
    const int sa1 = (lr + 64) * PITCH + kg * 4;
    const int sb0 = A_WORDS + lr * PITCH + kg * 4;   // + j*64*PITCH

    float4 ra0, ra1, rb[4];

    auto ldg_chunk = [&](int c) {
        const long o = (long)c * 8;
        ra0 = x4[ga0 + o];
        ra1 = x4[ga1 + o];
#pragma unroll
        for (int j = 0; j < 4; j++) rb[j] = w4[gb0 + (long)j * 4096 + o];
    };

    auto cvt4 = [](float4 v) {
        uint4 u;
        u.x = f2tf(v.x); u.y = f2tf(v.y); u.z = f2tf(v.z); u.w = f2tf(v.w);
        return u;
    };

    auto sts_chunk = [&](uint32_t* s) {
        *(uint4*)(s + sa0) = cvt4(ra0);
        *(uint4*)(s + sa1) = cvt4(ra1);
#pragma unroll
        for (int j = 0; j < 4; j++)
            *(uint4*)(s + sb0 + j * 64 * PITCH) = cvt4(rb[j]);
    };

    // ---------------- compute mapping ----------------
    // 16 warps: mw = wid/8 (two 64-row M halves), nw = wid%8 (32-wide N strips)
    const int wid = tid >> 5, l = tid & 31;
    const int mw = wid >> 3, nw = wid & 7;
    const int qr = l >> 2, ql = l & 3;

    int aoff[4], boff[4];
#pragma unroll
    for (int mi = 0; mi < 4; mi++)
        aoff[mi] = (mw * 64 + mi * 16 + qr) * PITCH + ql;
#pragma unroll
    for (int ni = 0; ni < 4; ni++)
        boff[ni] = A_WORDS + (nw * 32 + ni * 8 + qr) * PITCH + ql;

    float acc[4][4][4];
#pragma unroll
    for (int mi = 0; mi < 4; mi++)
#pragma unroll
        for (int ni = 0; ni < 4; ni++)
#pragma unroll
            for (int r = 0; r < 4; r++) acc[mi][ni][r] = 0.0f;

    auto compute_chunk = [&](const uint32_t* s) {
#pragma unroll
        for (int ks = 0; ks < 4; ks++) {
            uint32_t a[4][4], b[4][2];
#pragma unroll
            for (int mi = 0; mi < 4; mi++) {
                const int ba = aoff[mi] + ks * 8;
                a[mi][0] = s[ba];
                a[mi][1] = s[ba + 8 * PITCH];
                a[mi][2] = s[ba + 4];
                a[mi][3] = s[ba + 8 * PITCH + 4];
            }
#pragma unroll
            for (int ni = 0; ni < 4; ni++) {
                const int bb = boff[ni] + ks * 8;
                b[ni][0] = s[bb];
                b[ni][1] = s[bb + 4];
            }
#pragma unroll
            for (int mi = 0; mi < 4; mi++)
#pragma unroll
                for (int ni = 0; ni < 4; ni++)
                    mma_tf32(acc[mi][ni], a[mi], b[ni]);
        }
    };

    // ---------------- pipeline ----------------
    ldg_chunk(0);
    sts_chunk(stg0);
    ldg_chunk(1);
    __syncthreads();

#pragma unroll
    for (int c = 0; c < NCH; c++) {
        compute_chunk((c & 1) ? stg1 : stg0);
        if (c < NCH - 1) {
            sts_chunk(((c + 1) & 1) ? stg1 : stg0);   // regs from ldg(c+1)
            if (c < NCH - 2) ldg_chunk(c + 2);        // cover with next compute
        }
        __syncthreads();
    }

    // ---------------- epilogue: bias + relu, float2 stores ----------------
#pragma unroll
    for (int mi = 0; mi < 4; mi++) {
        const long r0 = m_base + mw * 64 + mi * 16 + qr;
#pragma unroll
        for (int ni = 0; ni < 4; ni++) {
            const int col = nw * 32 + ni * 8 + ql * 2;
            const float b0 = bsm[col], b1 = bsm[col + 1];
            float2 v0, v1;
            v0.x = fmaxf(acc[mi][ni][0] + b0, 0.0f);
            v0.y = fmaxf(acc[mi][ni][1] + b1, 0.0f);
            v1.x = fmaxf(acc[mi][ni][2] + b0, 0.0f);
            v1.y = fmaxf(acc[mi][ni][3] + b1, 0.0f);
            out2[r0 * 128 + (col >> 1)]       = v0;
            out2[(r0 + 8) * 128 + (col >> 1)] = v1;
        }
    }
}

extern "C" void kernel_launch(void* const* d_in, const int* in_sizes, int n_in,
                              void* d_out, int out_size) {
    const float* x = (const float*)d_in[0];   // [B, 256]
    const float* W = (const float*)d_in[1];   // [256, 256]
    const float* b = (const float*)d_in[2];   // [256]

    const int rows = in_sizes[0] / DIM;       // 131072
    const int grid = rows / TILE_M;           // 1024

    cudaFuncSetAttribute(gemm_bias_relu_mma,
                         cudaFuncAttributeMaxDynamicSharedMemorySize, SMEM_BYTES);
    gemm_bias_relu_mma<<<grid, THREADS, SMEM_BYTES>>>(
        (const float4*)x, (const float4*)W, b, (float2*)d_out);
}